// round 5
// baseline (speedup 1.0000x reference)
#include <cuda_runtime.h>
#include <cstdint>
#include <math.h>

// ---------------------------------------------------------------------------
// Problem constants
// ---------------------------------------------------------------------------
#define M_TOTAL 32768
#define NCODES  1024
#define KDIM    256
#define TOPM    3
#define KC      32                 // K per chunk
#define NCHUNK  (KDIM / KC)        // 8
#define MT      128                // CTA tile M
#define NT      128                // CTA tile N

// Fragment-image sizes (in 32-bit words) per (tile, chunk)
#define A_IMG_WORDS 4096           // 4 s * 8 mb * 32 lanes * 4 regs
#define B_IMG_WORDS 4096           // 4 s * 16 nb * 32 lanes * 2 regs

// ---------------------------------------------------------------------------
// Device scratch (no allocs allowed)
// ---------------------------------------------------------------------------
__device__ float g_Ahi[(size_t)M_TOTAL * KDIM];
__device__ float g_Alo[(size_t)M_TOTAL * KDIM];
__device__ float g_Bhi[(size_t)NCODES * KDIM];
__device__ float g_Blo[(size_t)NCODES * KDIM];
__device__ float2 g_cand[(size_t)M_TOTAL * 32 * TOPM];   // 32 n-slices x top3

// ---------------------------------------------------------------------------
// Helpers
// ---------------------------------------------------------------------------
__device__ __forceinline__ float tf32_rna(float x) {
    uint32_t u;
    asm("cvt.rna.tf32.f32 %0, %1;" : "=r"(u) : "f"(x));
    return __uint_as_float(u);
}
__device__ __forceinline__ uint32_t smem_u32(const void* p) {
    uint32_t a;
    asm("{ .reg .u64 t; cvta.to.shared.u64 t, %1; cvt.u32.u64 %0, t; }" : "=r"(a) : "l"(p));
    return a;
}
__device__ __forceinline__ void cp16(uint32_t dst, const void* src) {
    asm volatile("cp.async.cg.shared.global [%0], [%1], 16;" :: "r"(dst), "l"(src));
}

#define MMA_TF32(d, a, b) \
    asm volatile("mma.sync.aligned.m16n8k8.row.col.f32.tf32.tf32.f32 " \
        "{%0,%1,%2,%3}, {%4,%5,%6,%7}, {%8,%9}, {%0,%1,%2,%3};" \
        : "+f"((d)[0]), "+f"((d)[1]), "+f"((d)[2]), "+f"((d)[3]) \
        : "r"((a).x), "r"((a).y), "r"((a).z), "r"((a).w), "r"((b).x), "r"((b).y))

// ---------------------------------------------------------------------------
// Prep A: split q into tf32 hi/lo and store fragment-major images.
// grid = (NCHUNK, M_TOTAL/MT), 256 threads.
// A frag (m16n8k8 tf32): a0(r,c) a1(r+8,c) a2(r,c+4) a3(r+8,c+4),
//   r = lane>>2, c = lane&3. Image word = ((s*8+mb)*32 + lane)*4 + reg.
// ---------------------------------------------------------------------------
__global__ __launch_bounds__(256)
void prep_a_kernel(const float* __restrict__ A)
{
    __shared__ float ih[A_IMG_WORDS];
    __shared__ float il[A_IMG_WORDS];
    const int chunk = blockIdx.x, mt = blockIdx.y, tid = threadIdx.x;

#pragma unroll
    for (int i = 0; i < 4; i++) {
        int lin = tid + i * 256;            // 0..1023
        int row = lin >> 3;                 // 0..127
        int c4  = lin & 7;                  // k quad
        float4 v = *reinterpret_cast<const float4*>(
            &A[(size_t)(mt * MT + row) * KDIM + chunk * KC + c4 * 4]);
        int rm = row & 15, mb = row >> 4;
        int s  = c4 >> 1;
        int regBase = (c4 & 1) * 2 + (rm >= 8 ? 1 : 0);
        float vv[4] = {v.x, v.y, v.z, v.w};
#pragma unroll
        for (int e = 0; e < 4; e++) {
            float hi = tf32_rna(vv[e]);
            float lo = tf32_rna(vv[e] - hi);
            int lane = (rm & 7) * 4 + e;
            int dst  = ((s * 8 + mb) * 32 + lane) * 4 + regBase;
            ih[dst] = hi;
            il[dst] = lo;
        }
    }
    __syncthreads();
    size_t ob = ((size_t)mt * NCHUNK + chunk) * A_IMG_WORDS;
    float4* oh = reinterpret_cast<float4*>(&g_Ahi[ob]);
    float4* ol = reinterpret_cast<float4*>(&g_Alo[ob]);
    const float4* sh = reinterpret_cast<const float4*>(ih);
    const float4* sl = reinterpret_cast<const float4*>(il);
#pragma unroll
    for (int i = 0; i < 4; i++) {
        oh[tid + i * 256] = sh[tid + i * 256];
        ol[tid + i * 256] = sl[tid + i * 256];
    }
}

// ---------------------------------------------------------------------------
// Prep B: codes -> tf32 hi/lo fragment-major images.
// grid = (NCHUNK, NCODES/NT), 256 threads.
// B frag (k8n8): b0(k=lane&3, n=lane>>2), b1(k+4, n).
// Image word = ((s*16+nb)*32 + lane)*2 + reg.
// ---------------------------------------------------------------------------
__global__ __launch_bounds__(256)
void prep_b_kernel(const float* __restrict__ Bm)
{
    __shared__ float ih[B_IMG_WORDS];
    __shared__ float il[B_IMG_WORDS];
    const int chunk = blockIdx.x, nt = blockIdx.y, tid = threadIdx.x;

#pragma unroll
    for (int i = 0; i < 4; i++) {
        int lin = tid + i * 256;
        int n  = lin >> 3;                  // 0..127 code row
        int c4 = lin & 7;
        float4 v = *reinterpret_cast<const float4*>(
            &Bm[(size_t)(nt * NT + n) * KDIM + chunk * KC + c4 * 4]);
        int s = c4 >> 1;
        int breg = c4 & 1;                  // k%8 >= 4 -> b1
        int nb = n >> 3;
        float vv[4] = {v.x, v.y, v.z, v.w};
#pragma unroll
        for (int e = 0; e < 4; e++) {
            float hi = tf32_rna(vv[e]);
            float lo = tf32_rna(vv[e] - hi);
            int lane = (n & 7) * 4 + e;
            int dst  = ((s * 16 + nb) * 32 + lane) * 2 + breg;
            ih[dst] = hi;
            il[dst] = lo;
        }
    }
    __syncthreads();
    size_t ob = ((size_t)nt * NCHUNK + chunk) * B_IMG_WORDS;
    float4* oh = reinterpret_cast<float4*>(&g_Bhi[ob]);
    float4* ol = reinterpret_cast<float4*>(&g_Blo[ob]);
    const float4* sh = reinterpret_cast<const float4*>(ih);
    const float4* sl = reinterpret_cast<const float4*>(il);
#pragma unroll
    for (int i = 0; i < 4; i++) {
        oh[tid + i * 256] = sh[tid + i * 256];
        ol[tid + i * 256] = sl[tid + i * 256];
    }
}

// ---------------------------------------------------------------------------
// GEMM: sim = q @ codes^T via mma.sync tf32, 3-pass hi/lo split.
// 256 threads = 8 warps in a 2(m) x 4(n) grid; each warp 64m x 32n.
// cp.async 2-stage pipeline of fragment images. Fused top-3 candidates.
// Dynamic smem: 2 stages * 64KB.
// ---------------------------------------------------------------------------
#define STG_WORDS (4 * 4096)         // Ahi, Alo, Bhi, Blo images
#define SMEM_GEMM (2 * STG_WORDS * 4)  // 131072 bytes

struct Top3 {
    float v0, v1, v2;
    int   i0, i1, i2;
};
__device__ __forceinline__ void t3_init(Top3& t) {
    const float NEG_INF = -__int_as_float(0x7f800000);
    t.v0 = t.v1 = t.v2 = NEG_INF;
    t.i0 = t.i1 = t.i2 = 0x7fffffff;
}
__device__ __forceinline__ void t3_insert(Top3& t, float v, int idx) {
    bool g0 = (v > t.v0) || (v == t.v0 && idx < t.i0);
    bool g1 = (v > t.v1) || (v == t.v1 && idx < t.i1);
    bool g2 = (v > t.v2) || (v == t.v2 && idx < t.i2);
    if (g0)      { t.v2 = t.v1; t.i2 = t.i1; t.v1 = t.v0; t.i1 = t.i0; t.v0 = v; t.i0 = idx; }
    else if (g1) { t.v2 = t.v1; t.i2 = t.i1; t.v1 = v;  t.i1 = idx; }
    else if (g2) { t.v2 = v;  t.i2 = idx; }
}

__global__ __launch_bounds__(256, 1)
void vq_mma_kernel(float* __restrict__ C)
{
    extern __shared__ float sm[];
    const int tid = threadIdx.x;
    const int wid = tid >> 5;
    const int l   = tid & 31;
    const int wm  = wid >> 2;            // 0..1
    const int wn  = wid & 3;             // 0..3
    const int bx  = blockIdx.x;          // n tile (0..7)
    const int by  = blockIdx.y;          // m tile (0..255)
    const uint32_t sbase = smem_u32(sm);

    const float* srcA_hi = g_Ahi + ((size_t)by * NCHUNK) * A_IMG_WORDS;
    const float* srcA_lo = g_Alo + ((size_t)by * NCHUNK) * A_IMG_WORDS;
    const float* srcB_hi = g_Bhi + ((size_t)bx * NCHUNK) * B_IMG_WORDS;
    const float* srcB_lo = g_Blo + ((size_t)bx * NCHUNK) * B_IMG_WORDS;

    // issue one chunk's copies into stage st
    auto issue = [&](int c, int st) {
        uint32_t d = sbase + st * STG_WORDS * 4;
        const float* s0 = srcA_hi + c * A_IMG_WORDS;
        const float* s1 = srcA_lo + c * A_IMG_WORDS;
        const float* s2 = srcB_hi + c * B_IMG_WORDS;
        const float* s3 = srcB_lo + c * B_IMG_WORDS;
#pragma unroll
        for (int i = 0; i < 4; i++) {
            int w = (tid + i * 256) * 4;           // word offset
            cp16(d + 0 * 16384 + w * 4, s0 + w);
            cp16(d + 1 * 16384 + w * 4, s1 + w);
            cp16(d + 2 * 16384 + w * 4, s2 + w);
            cp16(d + 3 * 16384 + w * 4, s3 + w);
        }
        asm volatile("cp.async.commit_group;" ::: "memory");
    };

    float acc[4][4][4];
#pragma unroll
    for (int mb = 0; mb < 4; mb++)
#pragma unroll
        for (int nb = 0; nb < 4; nb++)
#pragma unroll
            for (int r = 0; r < 4; r++) acc[mb][nb][r] = 0.0f;

    issue(0, 0);
    issue(1, 1);

#pragma unroll 1
    for (int c = 0; c < NCHUNK; c++) {
        if (c == NCHUNK - 1) asm volatile("cp.async.wait_group 0;" ::: "memory");
        else                 asm volatile("cp.async.wait_group 1;" ::: "memory");
        __syncthreads();

        const float* S  = sm + (c & 1) * STG_WORDS;
        const float* Ah = S;
        const float* Al = S + 4096;
        const float* Bh = S + 8192;
        const float* Bl = S + 12288;

#pragma unroll
        for (int s = 0; s < 4; s++) {
            uint4 ah[4]; uint2 bh[4];
#pragma unroll
            for (int t = 0; t < 4; t++)
                ah[t] = *reinterpret_cast<const uint4*>(
                    &Ah[((s * 8 + wm * 4 + t) * 32 + l) * 4]);
#pragma unroll
            for (int t = 0; t < 4; t++)
                bh[t] = *reinterpret_cast<const uint2*>(
                    &Bh[((s * 16 + wn * 4 + t) * 32 + l) * 2]);
            // pass 1: hi * hi
#pragma unroll
            for (int mb = 0; mb < 4; mb++)
#pragma unroll
                for (int nb = 0; nb < 4; nb++) MMA_TF32(acc[mb][nb], ah[mb], bh[nb]);
            // pass 2: lo * hi
            {
                uint4 al[4];
#pragma unroll
                for (int t = 0; t < 4; t++)
                    al[t] = *reinterpret_cast<const uint4*>(
                        &Al[((s * 8 + wm * 4 + t) * 32 + l) * 4]);
#pragma unroll
                for (int mb = 0; mb < 4; mb++)
#pragma unroll
                    for (int nb = 0; nb < 4; nb++) MMA_TF32(acc[mb][nb], al[mb], bh[nb]);
            }
            // pass 3: hi * lo
            {
                uint2 bl[4];
#pragma unroll
                for (int t = 0; t < 4; t++)
                    bl[t] = *reinterpret_cast<const uint2*>(
                        &Bl[((s * 16 + wn * 4 + t) * 32 + l) * 2]);
#pragma unroll
                for (int mb = 0; mb < 4; mb++)
#pragma unroll
                    for (int nb = 0; nb < 4; nb++) MMA_TF32(acc[mb][nb], ah[mb], bl[nb]);
            }
        }
        __syncthreads();
        if (c + 2 < NCHUNK) issue(c + 2, c & 1);
    }

    // ---- Epilogue: store sim + per-row top-3 candidates from registers ----
    const int bm0 = by * MT;
    const int bn0 = bx * NT;
    const int rq  = l >> 2;          // quad row
    const int qc  = l & 3;           // quad col lane
    const int slice = bx * 4 + wn;   // global 32-col slice id

#pragma unroll
    for (int mb = 0; mb < 4; mb++) {
#pragma unroll
        for (int pair = 0; pair < 2; pair++) {
            int row = bm0 + wm * 64 + mb * 16 + rq + pair * 8;
            // local top3 of this thread's 8 values (cols ascending)
            Top3 t; t3_init(t);
#pragma unroll
            for (int nb = 0; nb < 4; nb++) {
                int colbase = bn0 + wn * 32 + nb * 8 + qc * 2;
                t3_insert(t, acc[mb][nb][pair * 2 + 0], colbase + 0);
                t3_insert(t, acc[mb][nb][pair * 2 + 1], colbase + 1);
            }
            // quad merge (lanes qc 0..3 share this row): xor 1, then xor 2
#pragma unroll
            for (int off = 1; off <= 2; off <<= 1) {
                float pv0 = __shfl_xor_sync(0xffffffffu, t.v0, off);
                float pv1 = __shfl_xor_sync(0xffffffffu, t.v1, off);
                float pv2 = __shfl_xor_sync(0xffffffffu, t.v2, off);
                int   pi0 = __shfl_xor_sync(0xffffffffu, t.i0, off);
                int   pi1 = __shfl_xor_sync(0xffffffffu, t.i1, off);
                int   pi2 = __shfl_xor_sync(0xffffffffu, t.i2, off);
                t3_insert(t, pv0, pi0);
                t3_insert(t, pv1, pi1);
                t3_insert(t, pv2, pi2);
            }
            if (qc == 0) {
                float2* cr = &g_cand[((size_t)row * 32 + slice) * 3];
                cr[0] = make_float2(t.v0, (float)t.i0);
                cr[1] = make_float2(t.v1, (float)t.i1);
                cr[2] = make_float2(t.v2, (float)t.i2);
            }
            // sim store (quad-contiguous 32B sectors)
            float* crow = &C[(size_t)row * NCODES + bn0 + wn * 32 + qc * 2];
#pragma unroll
            for (int nb = 0; nb < 4; nb++) {
                *reinterpret_cast<float2*>(&crow[nb * 8]) =
                    make_float2(acc[mb][nb][pair * 2 + 0], acc[mb][nb][pair * 2 + 1]);
            }
        }
    }
}

// ---------------------------------------------------------------------------
// Merge: 32 slices x top3 candidates per row -> final top3 + Gumbel softmax.
// ---------------------------------------------------------------------------
__global__ __launch_bounds__(256)
void vq_merge_kernel(const int* __restrict__ mask,
                     const float* __restrict__ u,
                     float* __restrict__ out_idx,
                     float* __restrict__ out_w)
{
    int row = blockIdx.x * 256 + threadIdx.x;
    int m = mask[row];
    if (m == 0) {
#pragma unroll
        for (int r = 0; r < 3; r++) {
            out_idx[row * 3 + r] = (float)r;
            out_w[row * 3 + r]   = 0.0f;
        }
        return;
    }
    Top3 t; t3_init(t);
    const float2* cr = &g_cand[(size_t)row * 96];
#pragma unroll 8
    for (int k = 0; k < 96; k++) {
        float2 c = cr[k];
        t3_insert(t, c.x, (int)c.y);
    }
    float tv[3] = {t.v0, t.v1, t.v2};
    int   ti[3] = {t.i0, t.i1, t.i2};
    float lg[3];
#pragma unroll
    for (int r = 0; r < 3; r++) {
        float uu = u[row * 3 + r];
        uu = fminf(fmaxf(uu, 1e-7f), 1.0f - 1e-7f);
        float inner = fmaxf(-logf(uu), 1e-7f);
        lg[r] = tv[r] - logf(inner);      // TAU = 1.0
    }
    float mx = fmaxf(lg[0], fmaxf(lg[1], lg[2]));
    float e0 = expf(lg[0] - mx);
    float e1 = expf(lg[1] - mx);
    float e2 = expf(lg[2] - mx);
    float inv = 1.0f / (e0 + e1 + e2);
#pragma unroll
    for (int r = 0; r < 3; r++) out_idx[row * 3 + r] = (float)ti[r];
    out_w[row * 3 + 0] = e0 * inv;
    out_w[row * 3 + 1] = e1 * inv;
    out_w[row * 3 + 2] = e2 * inv;
}

// ---------------------------------------------------------------------------
// Launch: d_out layout = [top_idx (M*3) | weights (M*3) | sim (M*K)]
// ---------------------------------------------------------------------------
extern "C" void kernel_launch(void* const* d_in, const int* in_sizes, int n_in,
                              void* d_out, int out_size)
{
    const float* q     = (const float*)d_in[0];
    const float* codes = (const float*)d_in[1];
    const int*   mask  = (const int*)  d_in[2];
    const float* u     = (const float*)d_in[3];

    float* out     = (float*)d_out;
    float* out_idx = out;
    float* out_w   = out + (size_t)M_TOTAL * TOPM;
    float* sim     = out + (size_t)2 * M_TOTAL * TOPM;

    cudaFuncSetAttribute(vq_mma_kernel,
                         cudaFuncAttributeMaxDynamicSharedMemorySize, SMEM_GEMM);

    prep_a_kernel<<<dim3(NCHUNK, M_TOTAL / MT), 256>>>(q);
    prep_b_kernel<<<dim3(NCHUNK, NCODES / NT), 256>>>(codes);

    dim3 grid(NCODES / NT, M_TOTAL / MT);   // (8, 256), x fastest: n-CTAs share A in L2
    vq_mma_kernel<<<grid, 256, SMEM_GEMM>>>(sim);

    vq_merge_kernel<<<M_TOTAL / 256, 256>>>(mask, u, out_idx, out_w);
}

// round 6
// speedup vs baseline: 1.2163x; 1.2163x over previous
#include <cuda_runtime.h>
#include <cstdint>
#include <math.h>

// Problem constants
#define BATCH   8
#define SEQ     4096
#define M_TOTAL (BATCH * SEQ)   // 32768
#define NCODES  1024
#define KDIM    256
#define TOPM    3

// GEMM tiling
#define BM 128
#define BN 128
#define BK 16
#define NTILES (NCODES / BN)    // 8

// Candidate scratch: top3 (val,idx) per row per N-tile
__device__ float2 g_cand[(size_t)M_TOTAL * NTILES * TOPM];

// ---------------------------------------------------------------------------
// Packed fp32x2 helpers (bit-exact vs two fmaf)
// ---------------------------------------------------------------------------
__device__ __forceinline__ unsigned long long pack2(float x) {
    unsigned long long r;
    asm("mov.b64 %0, {%1, %1};" : "=l"(r) : "f"(x));
    return r;
}
__device__ __forceinline__ void fma2(unsigned long long& acc,
                                     unsigned long long a,
                                     unsigned long long b) {
    asm("fma.rn.f32x2 %0, %1, %2, %0;" : "+l"(acc) : "l"(a), "l"(b));
}
__device__ __forceinline__ float2 unpack2(unsigned long long v) {
    float2 f;
    asm("mov.b64 {%0, %1}, %2;" : "=f"(f.x), "=f"(f.y) : "l"(v));
    return f;
}

// ---------------------------------------------------------------------------
// Top-3 insertion (tiebreak: smaller index wins, matching jax.lax.top_k)
// ---------------------------------------------------------------------------
struct Top3 { float v0, v1, v2; int i0, i1, i2; };
__device__ __forceinline__ void t3_init(Top3& t) {
    const float NEG_INF = -__int_as_float(0x7f800000);
    t.v0 = t.v1 = t.v2 = NEG_INF;
    t.i0 = t.i1 = t.i2 = 0x7fffffff;
}
// strict '>' version: valid when indices arrive in ascending order
__device__ __forceinline__ void t3_insert_asc(Top3& t, float v, int idx) {
    if (v > t.v0)      { t.v2 = t.v1; t.i2 = t.i1; t.v1 = t.v0; t.i1 = t.i0; t.v0 = v; t.i0 = idx; }
    else if (v > t.v1) { t.v2 = t.v1; t.i2 = t.i1; t.v1 = v;  t.i1 = idx; }
    else if (v > t.v2) { t.v2 = v;  t.i2 = idx; }
}
// tiebreak version: for cross-lane merges
__device__ __forceinline__ void t3_insert_tb(Top3& t, float v, int idx) {
    bool g0 = (v > t.v0) || (v == t.v0 && idx < t.i0);
    bool g1 = (v > t.v1) || (v == t.v1 && idx < t.i1);
    bool g2 = (v > t.v2) || (v == t.v2 && idx < t.i2);
    if (g0)      { t.v2 = t.v1; t.i2 = t.i1; t.v1 = t.v0; t.i1 = t.i0; t.v0 = v; t.i0 = idx; }
    else if (g1) { t.v2 = t.v1; t.i2 = t.i1; t.v1 = v;  t.i1 = idx; }
    else if (g2) { t.v2 = v;  t.i2 = idx; }
}
__device__ __forceinline__ void t3_merge_shfl(Top3& t, int off) {
    float pv0 = __shfl_xor_sync(0xffffffffu, t.v0, off);
    float pv1 = __shfl_xor_sync(0xffffffffu, t.v1, off);
    float pv2 = __shfl_xor_sync(0xffffffffu, t.v2, off);
    int   pi0 = __shfl_xor_sync(0xffffffffu, t.i0, off);
    int   pi1 = __shfl_xor_sync(0xffffffffu, t.i1, off);
    int   pi2 = __shfl_xor_sync(0xffffffffu, t.i2, off);
    t3_insert_tb(t, pv0, pi0);
    t3_insert_tb(t, pv1, pi1);
    t3_insert_tb(t, pv2, pi2);
}

// ---------------------------------------------------------------------------
// Kernel 1: sim = q @ codes^T via fma.f32x2 + fused per-row top-3 candidates.
// ---------------------------------------------------------------------------
__global__ __launch_bounds__(256, 2)
void vq_sgemm_kernel(const float* __restrict__ A,    // [M_TOTAL, KDIM]
                     const float* __restrict__ Bm,   // [NCODES,  KDIM]
                     float* __restrict__ C)          // [M_TOTAL, NCODES]
{
    __shared__ float As[BK][BM + 4];   // stride 132 floats
    __shared__ float Bs[BK][BN + 4];

    const int bn0 = blockIdx.x * BN;
    const int bm0 = blockIdx.y * BM;
    const int tid = threadIdx.x;
    const int tx  = tid & 15;          // 0..15 -> N
    const int ty  = tid >> 4;          // 0..15 -> M

    const int lrow0 = tid >> 2;              // 0..63
    const int lrow1 = lrow0 + 64;
    const int lc4   = (tid & 3) * 4;

    const float* Aptr0 = &A[(size_t)(bm0 + lrow0) * KDIM + lc4];
    const float* Aptr1 = &A[(size_t)(bm0 + lrow1) * KDIM + lc4];
    const float* Bptr0 = &Bm[(size_t)(bn0 + lrow0) * KDIM + lc4];
    const float* Bptr1 = &Bm[(size_t)(bn0 + lrow1) * KDIM + lc4];

    unsigned long long acc2[8][4];
#pragma unroll
    for (int i = 0; i < 8; i++)
#pragma unroll
        for (int j = 0; j < 4; j++) acc2[i][j] = 0ull;

    float4 pa0 = *reinterpret_cast<const float4*>(Aptr0);
    float4 pa1 = *reinterpret_cast<const float4*>(Aptr1);
    float4 pb0 = *reinterpret_cast<const float4*>(Bptr0);
    float4 pb1 = *reinterpret_cast<const float4*>(Bptr1);

#pragma unroll 1
    for (int c = 0; c < KDIM / BK; c++) {
        As[lc4 + 0][lrow0] = pa0.x; As[lc4 + 1][lrow0] = pa0.y;
        As[lc4 + 2][lrow0] = pa0.z; As[lc4 + 3][lrow0] = pa0.w;
        As[lc4 + 0][lrow1] = pa1.x; As[lc4 + 1][lrow1] = pa1.y;
        As[lc4 + 2][lrow1] = pa1.z; As[lc4 + 3][lrow1] = pa1.w;
        Bs[lc4 + 0][lrow0] = pb0.x; Bs[lc4 + 1][lrow0] = pb0.y;
        Bs[lc4 + 2][lrow0] = pb0.z; Bs[lc4 + 3][lrow0] = pb0.w;
        Bs[lc4 + 0][lrow1] = pb1.x; Bs[lc4 + 1][lrow1] = pb1.y;
        Bs[lc4 + 2][lrow1] = pb1.z; Bs[lc4 + 3][lrow1] = pb1.w;
        __syncthreads();

        if (c + 1 < KDIM / BK) {
            int koff = (c + 1) * BK;
            pa0 = *reinterpret_cast<const float4*>(Aptr0 + koff);
            pa1 = *reinterpret_cast<const float4*>(Aptr1 + koff);
            pb0 = *reinterpret_cast<const float4*>(Bptr0 + koff);
            pb1 = *reinterpret_cast<const float4*>(Bptr1 + koff);
        }

#pragma unroll
        for (int kk = 0; kk < BK; kk++) {
            float4 a0 = *reinterpret_cast<const float4*>(&As[kk][ty * 4]);
            float4 a1 = *reinterpret_cast<const float4*>(&As[kk][64 + ty * 4]);
            ulonglong2 bp = *reinterpret_cast<const ulonglong2*>(&Bs[kk][tx * 4]);
            ulonglong2 bq = *reinterpret_cast<const ulonglong2*>(&Bs[kk][64 + tx * 4]);

            float av[8] = {a0.x, a0.y, a0.z, a0.w, a1.x, a1.y, a1.z, a1.w};
#pragma unroll
            for (int i = 0; i < 8; i++) {
                unsigned long long ap = pack2(av[i]);
                fma2(acc2[i][0], ap, bp.x);
                fma2(acc2[i][1], ap, bp.y);
                fma2(acc2[i][2], ap, bq.x);
                fma2(acc2[i][3], ap, bq.y);
            }
        }
        __syncthreads();
    }

    // ---- Epilogue: sim stores + fused per-row top-3 candidates ----
    // Thread's rows: {ty*4+ii (ih=0), 64+ty*4+ii (ih=1)};
    // cols: {tx*4+0..3, 64+tx*4+0..3}. The 16 threads with equal ty share each
    // row and occupy a 16-aligned lane group -> xor-shfl 1,2,4,8 merges them.
#pragma unroll
    for (int ih = 0; ih < 2; ih++) {
#pragma unroll
        for (int ii = 0; ii < 4; ii++) {
            int i = ih * 4 + ii;
            int row = bm0 + ih * 64 + ty * 4 + ii;
            float2 c0 = unpack2(acc2[i][0]);
            float2 c1 = unpack2(acc2[i][1]);
            float2 c2 = unpack2(acc2[i][2]);
            float2 c3 = unpack2(acc2[i][3]);

            float* crow = &C[(size_t)row * NCODES + bn0];
            *reinterpret_cast<float4*>(&crow[tx * 4]) =
                make_float4(c0.x, c0.y, c1.x, c1.y);
            *reinterpret_cast<float4*>(&crow[64 + tx * 4]) =
                make_float4(c2.x, c2.y, c3.x, c3.y);

            Top3 t; t3_init(t);
            int b0 = bn0 + tx * 4;
            int b1 = bn0 + 64 + tx * 4;
            t3_insert_asc(t, c0.x, b0 + 0);
            t3_insert_asc(t, c0.y, b0 + 1);
            t3_insert_asc(t, c1.x, b0 + 2);
            t3_insert_asc(t, c1.y, b0 + 3);
            t3_insert_asc(t, c2.x, b1 + 0);
            t3_insert_asc(t, c2.y, b1 + 1);
            t3_insert_asc(t, c3.x, b1 + 2);
            t3_insert_asc(t, c3.y, b1 + 3);

            t3_merge_shfl(t, 1);
            t3_merge_shfl(t, 2);
            t3_merge_shfl(t, 4);
            t3_merge_shfl(t, 8);

            if (tx == 0) {
                float2* cr = &g_cand[((size_t)row * NTILES + blockIdx.x) * 3];
                cr[0] = make_float2(t.v0, (float)t.i0);
                cr[1] = make_float2(t.v1, (float)t.i1);
                cr[2] = make_float2(t.v2, (float)t.i2);
            }
        }
    }
}

// ---------------------------------------------------------------------------
// Kernel 2: merge 8 slices x top3 per row (8 threads/row) + Gumbel softmax.
// ---------------------------------------------------------------------------
__global__ __launch_bounds__(256)
void vq_merge_kernel(const int*   __restrict__ mask,
                     const float* __restrict__ u,
                     float* __restrict__ out_idx,
                     float* __restrict__ out_w)
{
    int g    = blockIdx.x * 256 + threadIdx.x;
    int row  = g >> 3;
    int s    = g & 7;

    Top3 t; t3_init(t);
    const float2* cr = &g_cand[((size_t)row * NTILES + s) * 3];
    float2 c0 = cr[0], c1 = cr[1], c2 = cr[2];
    t3_insert_tb(t, c0.x, (int)c0.y);
    t3_insert_tb(t, c1.x, (int)c1.y);
    t3_insert_tb(t, c2.x, (int)c2.y);

    t3_merge_shfl(t, 1);
    t3_merge_shfl(t, 2);
    t3_merge_shfl(t, 4);

    if (s == 0) {
        int m = mask[row];
        if (m == 0) {
            // all sims masked to equal -10000 -> lax.top_k picks idx 0,1,2
#pragma unroll
            for (int r = 0; r < 3; r++) {
                out_idx[row * 3 + r] = (float)r;
                out_w[row * 3 + r]   = 0.0f;
            }
        } else {
            float tv[3] = {t.v0, t.v1, t.v2};
            int   ti[3] = {t.i0, t.i1, t.i2};
            float lg[3];
#pragma unroll
            for (int r = 0; r < 3; r++) {
                float uu = u[row * 3 + r];
                uu = fminf(fmaxf(uu, 1e-7f), 1.0f - 1e-7f);
                float inner = fmaxf(-logf(uu), 1e-7f);
                lg[r] = tv[r] - logf(inner);      // TAU = 1.0
            }
            float mx = fmaxf(lg[0], fmaxf(lg[1], lg[2]));
            float e0 = expf(lg[0] - mx);
            float e1 = expf(lg[1] - mx);
            float e2 = expf(lg[2] - mx);
            float inv = 1.0f / (e0 + e1 + e2);
#pragma unroll
            for (int r = 0; r < 3; r++) out_idx[row * 3 + r] = (float)ti[r];
            out_w[row * 3 + 0] = e0 * inv;
            out_w[row * 3 + 1] = e1 * inv;
            out_w[row * 3 + 2] = e2 * inv;
        }
    }
}

// ---------------------------------------------------------------------------
// Launch: d_out layout = [top_idx (M*3) | weights (M*3) | sim (M*K)]
// ---------------------------------------------------------------------------
extern "C" void kernel_launch(void* const* d_in, const int* in_sizes, int n_in,
                              void* d_out, int out_size)
{
    const float* q     = (const float*)d_in[0];
    const float* codes = (const float*)d_in[1];
    const int*   mask  = (const int*)  d_in[2];
    const float* u     = (const float*)d_in[3];

    float* out     = (float*)d_out;
    float* out_idx = out;
    float* out_w   = out + (size_t)M_TOTAL * TOPM;
    float* sim     = out + (size_t)2 * M_TOTAL * TOPM;

    dim3 grid(NCODES / BN, M_TOTAL / BM);
    vq_sgemm_kernel<<<grid, 256>>>(q, codes, sim);

    vq_merge_kernel<<<(M_TOTAL * 8) / 256, 256>>>(mask, u, out_idx, out_w);
}

// round 8
// speedup vs baseline: 1.4045x; 1.1548x over previous
#include <cuda_runtime.h>
#include <math.h>

// Problem constants
#define BATCH   8
#define SEQ     4096
#define M_TOTAL (BATCH * SEQ)   // 32768
#define NCODES  1024
#define KDIM    256
#define TOPM    3

// GEMM tiling
#define BM 128
#define BN 128
#define BK 16

// ---------------------------------------------------------------------------
// Packed fp32x2 helpers (sm_100 Blackwell dual-lane FP32, bit-exact vs fmaf)
// ---------------------------------------------------------------------------
__device__ __forceinline__ unsigned long long pack2(float x) {
    unsigned long long r;
    asm("mov.b64 %0, {%1, %1};" : "=l"(r) : "f"(x));
    return r;
}
__device__ __forceinline__ void fma2(unsigned long long& acc,
                                     unsigned long long a,
                                     unsigned long long b) {
    asm("fma.rn.f32x2 %0, %1, %2, %0;" : "+l"(acc) : "l"(a), "l"(b));
}
__device__ __forceinline__ float2 unpack2(unsigned long long v) {
    float2 f;
    asm("mov.b64 {%0, %1}, %2;" : "=f"(f.x), "=f"(f.y) : "l"(v));
    return f;
}

// ---------------------------------------------------------------------------
// Kernel 1: sim = q @ codes^T   (M=32768, N=1024, K=256), fp32 via fma.f32x2
// UNCHANGED from the 367.7us best: at the FFMA2 RF-banking roofline.
// ---------------------------------------------------------------------------
__global__ __launch_bounds__(256, 2)
void vq_sgemm_kernel(const float* __restrict__ A,    // [M_TOTAL, KDIM]
                     const float* __restrict__ Bm,   // [NCODES,  KDIM]
                     float* __restrict__ C)          // [M_TOTAL, NCODES]
{
    __shared__ float As[BK][BM + 4];   // stride 132 floats
    __shared__ float Bs[BK][BN + 4];

    const int bn0 = blockIdx.x * BN;
    const int bm0 = blockIdx.y * BM;
    const int tid = threadIdx.x;
    const int tx  = tid & 15;          // 0..15 -> N
    const int ty  = tid >> 4;          // 0..15 -> M

    const int lrow0 = tid >> 2;              // 0..63
    const int lrow1 = lrow0 + 64;            // 64..127
    const int lc4   = (tid & 3) * 4;         // 0,4,8,12

    const float* Aptr0 = &A[(size_t)(bm0 + lrow0) * KDIM + lc4];
    const float* Aptr1 = &A[(size_t)(bm0 + lrow1) * KDIM + lc4];
    const float* Bptr0 = &Bm[(size_t)(bn0 + lrow0) * KDIM + lc4];
    const float* Bptr1 = &Bm[(size_t)(bn0 + lrow1) * KDIM + lc4];

    unsigned long long acc2[8][4];
#pragma unroll
    for (int i = 0; i < 8; i++)
#pragma unroll
        for (int j = 0; j < 4; j++) acc2[i][j] = 0ull;

    // Prologue: load chunk 0
    float4 pa0 = *reinterpret_cast<const float4*>(Aptr0);
    float4 pa1 = *reinterpret_cast<const float4*>(Aptr1);
    float4 pb0 = *reinterpret_cast<const float4*>(Bptr0);
    float4 pb1 = *reinterpret_cast<const float4*>(Bptr1);

#pragma unroll 1
    for (int c = 0; c < KDIM / BK; c++) {
        As[lc4 + 0][lrow0] = pa0.x; As[lc4 + 1][lrow0] = pa0.y;
        As[lc4 + 2][lrow0] = pa0.z; As[lc4 + 3][lrow0] = pa0.w;
        As[lc4 + 0][lrow1] = pa1.x; As[lc4 + 1][lrow1] = pa1.y;
        As[lc4 + 2][lrow1] = pa1.z; As[lc4 + 3][lrow1] = pa1.w;
        Bs[lc4 + 0][lrow0] = pb0.x; Bs[lc4 + 1][lrow0] = pb0.y;
        Bs[lc4 + 2][lrow0] = pb0.z; Bs[lc4 + 3][lrow0] = pb0.w;
        Bs[lc4 + 0][lrow1] = pb1.x; Bs[lc4 + 1][lrow1] = pb1.y;
        Bs[lc4 + 2][lrow1] = pb1.z; Bs[lc4 + 3][lrow1] = pb1.w;
        __syncthreads();

        if (c + 1 < KDIM / BK) {
            int koff = (c + 1) * BK;
            pa0 = *reinterpret_cast<const float4*>(Aptr0 + koff);
            pa1 = *reinterpret_cast<const float4*>(Aptr1 + koff);
            pb0 = *reinterpret_cast<const float4*>(Bptr0 + koff);
            pb1 = *reinterpret_cast<const float4*>(Bptr1 + koff);
        }

#pragma unroll
        for (int kk = 0; kk < BK; kk++) {
            float4 a0 = *reinterpret_cast<const float4*>(&As[kk][ty * 4]);
            float4 a1 = *reinterpret_cast<const float4*>(&As[kk][64 + ty * 4]);
            ulonglong2 bp = *reinterpret_cast<const ulonglong2*>(&Bs[kk][tx * 4]);
            ulonglong2 bq = *reinterpret_cast<const ulonglong2*>(&Bs[kk][64 + tx * 4]);

            float av[8] = {a0.x, a0.y, a0.z, a0.w, a1.x, a1.y, a1.z, a1.w};
#pragma unroll
            for (int i = 0; i < 8; i++) {
                unsigned long long ap = pack2(av[i]);
                fma2(acc2[i][0], ap, bp.x);
                fma2(acc2[i][1], ap, bp.y);
                fma2(acc2[i][2], ap, bq.x);
                fma2(acc2[i][3], ap, bq.y);
            }
        }
        __syncthreads();
    }

#pragma unroll
    for (int ih = 0; ih < 2; ih++) {
#pragma unroll
        for (int ii = 0; ii < 4; ii++) {
            int i = ih * 4 + ii;
            int row = bm0 + ih * 64 + ty * 4 + ii;
            float* crow = &C[(size_t)row * NCODES + bn0];
            float2 c0 = unpack2(acc2[i][0]);
            float2 c1 = unpack2(acc2[i][1]);
            float2 c2 = unpack2(acc2[i][2]);
            float2 c3 = unpack2(acc2[i][3]);
            *reinterpret_cast<float4*>(&crow[tx * 4]) =
                make_float4(c0.x, c0.y, c1.x, c1.y);
            *reinterpret_cast<float4*>(&crow[64 + tx * 4]) =
                make_float4(c2.x, c2.y, c3.x, c3.y);
        }
    }
}

// ---------------------------------------------------------------------------
// Kernel 2: per-row masked top-3 + Gumbel softmax. One warp per row.
// Optimized: register-cached row (MLP=8) + quad-max prefilter that moves
// the common-path work onto the fma pipe and skips the ALU insert chain.
// ---------------------------------------------------------------------------
__global__ __launch_bounds__(256)
void vq_topk_kernel(const float* __restrict__ sim,   // [M_TOTAL, NCODES]
                    const int*   __restrict__ mask,  // [M_TOTAL]
                    const float* __restrict__ u,     // [M_TOTAL, 3]
                    float* __restrict__ out_idx,     // [M_TOTAL, 3] (as float)
                    float* __restrict__ out_w)       // [M_TOTAL, 3]
{
    const int row  = blockIdx.x * 8 + (threadIdx.x >> 5);
    const int lane = threadIdx.x & 31;
    const float* srow = sim + (size_t)row * NCODES;

    // Load entire per-lane slice up front: 8 x LDG.128 in flight.
    float4 r[8];
#pragma unroll
    for (int t = 0; t < 8; t++)
        r[t] = *reinterpret_cast<const float4*>(&srow[t * 128 + lane * 4]);

    const float NEG_INF = -__int_as_float(0x7f800000);  // -inf
    float v0 = NEG_INF, v1 = NEG_INF, v2 = NEG_INF;
    int   i0 = 0x7fffffff, i1 = 0x7fffffff, i2 = 0x7fffffff;

    // Within-lane index order is strictly increasing, so strict '>' keeps the
    // smaller index on ties; skipping when quad-max <= v2 is tiebreak-safe.
#pragma unroll
    for (int t = 0; t < 8; t++) {
        float4 v4 = r[t];
        float m = fmaxf(fmaxf(v4.x, v4.y), fmaxf(v4.z, v4.w));
        if (m > v2) {
            int base = t * 128 + lane * 4;
            float vv[4] = {v4.x, v4.y, v4.z, v4.w};
#pragma unroll
            for (int e = 0; e < 4; e++) {
                float v = vv[e];
                int idx = base + e;
                if (v > v0)      { v2 = v1; i2 = i1; v1 = v0; i1 = i0; v0 = v; i0 = idx; }
                else if (v > v1) { v2 = v1; i2 = i1; v1 = v;  i1 = idx; }
                else if (v > v2) { v2 = v;  i2 = idx; }
            }
        }
    }

    // Warp merge: 3 rounds of (value, index) arg-max with smaller-index
    // tie-break. Each lane keeps a cursor into its sorted local top-3.
    float lv[3] = {v0, v1, v2};
    int   li[3] = {i0, i1, i2};
    float tv[3];
    int   ti[3];
    int p = 0;
#pragma unroll
    for (int rr = 0; rr < 3; rr++) {
        float bv = (p < 3) ? lv[p] : NEG_INF;
        int   bi = (p < 3) ? li[p] : 0x7fffffff;
#pragma unroll
        for (int off = 16; off > 0; off >>= 1) {
            float ov = __shfl_xor_sync(0xffffffffu, bv, off);
            int   oi = __shfl_xor_sync(0xffffffffu, bi, off);
            if (ov > bv || (ov == bv && oi < bi)) { bv = ov; bi = oi; }
        }
        tv[rr] = bv; ti[rr] = bi;
        if (p < 3 && li[p] == bi) p++;   // winner lane advances its cursor
    }

    if (lane == 0) {
        int m = mask[row];
        if (m == 0) {
            // All sims masked to -10000 (equal): lax.top_k -> indices 0,1,2;
            // weights zeroed by the mask.
#pragma unroll
            for (int rr = 0; rr < 3; rr++) {
                out_idx[row * 3 + rr] = (float)rr;
                out_w[row * 3 + rr]   = 0.0f;
            }
        } else {
            float l[3];
#pragma unroll
            for (int rr = 0; rr < 3; rr++) {
                float uu = u[row * 3 + rr];
                uu = fminf(fmaxf(uu, 1e-7f), 1.0f - 1e-7f);
                float inner = fmaxf(-logf(uu), 1e-7f);
                float g = -logf(inner);
                l[rr] = tv[rr] + g;          // TAU = 1.0
            }
            float mx = fmaxf(l[0], fmaxf(l[1], l[2]));
            float e0 = expf(l[0] - mx);
            float e1 = expf(l[1] - mx);
            float e2 = expf(l[2] - mx);
            float inv = 1.0f / (e0 + e1 + e2);
#pragma unroll
            for (int rr = 0; rr < 3; rr++) {
                out_idx[row * 3 + rr] = (float)ti[rr];
            }
            out_w[row * 3 + 0] = e0 * inv;
            out_w[row * 3 + 1] = e1 * inv;
            out_w[row * 3 + 2] = e2 * inv;
        }
    }
}

// ---------------------------------------------------------------------------
// Launch: d_out layout = [top_idx (B*N*3) | weights (B*N*3) | sim (B*N*K)]
// ---------------------------------------------------------------------------
extern "C" void kernel_launch(void* const* d_in, const int* in_sizes, int n_in,
                              void* d_out, int out_size)
{
    const float* q     = (const float*)d_in[0];   // [8,4096,256]
    const float* codes = (const float*)d_in[1];   // [1024,256]
    const int*   mask  = (const int*)  d_in[2];   // [8,4096]
    const float* u     = (const float*)d_in[3];   // [8,4096,3]

    float* out      = (float*)d_out;
    float* out_idx  = out;
    float* out_w    = out + (size_t)M_TOTAL * TOPM;
    float* sim      = out + (size_t)2 * M_TOTAL * TOPM;

    dim3 grid(NCODES / BN, M_TOTAL / BM);
    vq_sgemm_kernel<<<grid, 256>>>(q, codes, sim);

    vq_topk_kernel<<<M_TOTAL / 8, 256>>>(sim, mask, u, out_idx, out_w);
}